// round 2
// baseline (speedup 1.0000x reference)
#include <cuda_runtime.h>
#include <cuda_bf16.h>
#include <cstdint>

#define N_ROIS   32768
#define N_GT     1024
#define N_IMAGES 8

// Compacted (bucketed-by-batch) GT storage.
__device__ float4 g_cbox[N_GT];   // x1, y1, x2+1, y2+1  (stable original order within batch)
__device__ float  g_carea[N_GT];  // (x2-x1+1)*(y2-y1+1)
__device__ float  g_clab[N_GT];   // class label
__device__ int    g_off[N_IMAGES + 1];

// ---------------------------------------------------------------------------
// Kernel 1: stable bucket of 1024 GTs by batch index (8 warps, warp w = batch w).
// ---------------------------------------------------------------------------
__global__ void __launch_bounds__(256) bucket_kernel(const float* __restrict__ gt,
                                                     const int* __restrict__ gb) {
    __shared__ int scnt[N_IMAGES];
    __shared__ int soff[N_IMAGES + 1];
    const int w    = threadIdx.x >> 5;
    const int lane = threadIdx.x & 31;

    int cnt = 0;
    for (int j0 = 0; j0 < N_GT; j0 += 32) {
        int b = gb[j0 + lane];
        unsigned m = __ballot_sync(0xffffffffu, b == w);
        cnt += __popc(m);
    }
    if (lane == 0) scnt[w] = cnt;
    __syncthreads();

    if (threadIdx.x == 0) {
        int o = 0;
        for (int b = 0; b < N_IMAGES; b++) { soff[b] = o; o += scnt[b]; }
        soff[N_IMAGES] = o;
        for (int b = 0; b <= N_IMAGES; b++) g_off[b] = soff[b];
    }
    __syncthreads();

    int pos = soff[w];
    for (int j0 = 0; j0 < N_GT; j0 += 32) {
        int j = j0 + lane;
        int b = gb[j];
        bool mine = (b == w);
        unsigned m = __ballot_sync(0xffffffffu, mine);
        if (mine) {
            int idx = pos + __popc(m & ((1u << lane) - 1u));
            const float* p = gt + 5 * j;
            float x1 = p[0], y1 = p[1], x2 = p[2], y2 = p[3], cls = p[4];
            g_cbox[idx]  = make_float4(x1, y1, x2 + 1.0f, y2 + 1.0f);
            g_carea[idx] = ((x2 - x1) + 1.0f) * ((y2 - y1) + 1.0f);
            g_clab[idx]  = cls;
        }
        pos += __popc(m);
    }
}

// ---------------------------------------------------------------------------
// Kernel 2: per-ROI division-free argmax IoU over its batch bucket + regression.
// One thread per ROI; GT buckets in shared memory (24KB, broadcast reads).
// ---------------------------------------------------------------------------
__global__ void __launch_bounds__(256) roitarget_kernel(const float* __restrict__ rois,
                                                        const int* __restrict__ rb,
                                                        float* __restrict__ out) {
    __shared__ float4 sbox[N_GT];
    __shared__ float  sarea[N_GT];
    __shared__ float  slab[N_GT];
    __shared__ int    soff[N_IMAGES + 1];

    const int tid = threadIdx.x;
    for (int j = tid; j < N_GT; j += 256) {
        sbox[j]  = g_cbox[j];
        sarea[j] = g_carea[j];
        slab[j]  = g_clab[j];
    }
    if (tid <= N_IMAGES) soff[tid] = g_off[tid];
    __syncthreads();

    const int i = blockIdx.x * 256 + tid;
    const float* r = rois + 5 * i;
    const float rx1 = r[0], ry1 = r[1], rx2 = r[2], ry2 = r[3];
    const float rx2p = rx2 + 1.0f;
    const float ry2p = ry2 + 1.0f;
    const float ew = rx2p - rx1;     // (x2-x1)+1 vs (x2+1)-x1: sub-ulp difference, tolerated
    const float eh = ry2p - ry1;
    const float area_r = ((rx2 - rx1) + 1.0f) * ((ry2 - ry1) + 1.0f);

    const int b  = rb[i];
    const int j0 = soff[b];
    const int j1 = soff[b + 1];

    // Sentinel = IoU 0. Pairs with inter <= 0 can never win.
    float bi = 0.0f;   // best intersection
    float bu = 1.0f;   // best union
    int   bj = -1;

    #pragma unroll 4
    for (int j = j0; j < j1; j++) {
        float4 g  = sbox[j];
        float ag  = sarea[j];
        float iw  = fminf(rx2p, g.z) - fmaxf(rx1, g.x);
        float ih  = fminf(ry2p, g.w) - fmaxf(ry1, g.y);
        float inter = fmaxf(iw, 0.0f) * ih;
        float uni   = (area_r + ag) - inter;
        bool better = inter * bu > bi * uni;   // iou_j > iou_best (cross-mult)
        bi = better ? inter : bi;
        bu = better ? uni   : bu;
        bj = better ? j     : bj;
    }

    const float iou = bi / bu;                 // one IEEE div per thread
    const bool  fg  = (bj >= 0) && (iou >= 0.5f);

    float lbl = 0.0f, dx = 0.0f, dy = 0.0f, dw = 0.0f, dh = 0.0f, wgt = 0.0f;
    if (fg) {
        float4 g = sbox[bj];
        float gw  = g.z - g.x;                 // (x2+1) - x1
        float gh  = g.w - g.y;
        float gcx = g.x + 0.5f * gw;
        float gcy = g.y + 0.5f * gh;
        float ecx = rx1 + 0.5f * ew;
        float ecy = ry1 + 0.5f * eh;
        dx = (gcx - ecx) / ew;
        dy = (gcy - ecy) / eh;
        dw = logf(gw / ew);
        dh = logf(gh / eh);
        lbl = slab[bj];
        wgt = 1.0f;
    }

    // Layout: labels[N] | deltas[N][4] | bbwgts[N][1]
    out[i] = lbl;
    reinterpret_cast<float4*>(out + N_ROIS)[i] = make_float4(dx, dy, dw, dh);
    out[N_ROIS * 5 + i] = wgt;
}

extern "C" void kernel_launch(void* const* d_in, const int* in_sizes, int n_in,
                              void* d_out, int out_size) {
    const float* rois = (const float*)d_in[0];
    const int*   rb   = (const int*)d_in[1];
    const float* gt   = (const float*)d_in[2];
    const int*   gb   = (const int*)d_in[3];
    float* out = (float*)d_out;

    bucket_kernel<<<1, 256>>>(gt, gb);
    roitarget_kernel<<<N_ROIS / 256, 256>>>(rois, rb, out);
}